// round 1
// baseline (speedup 1.0000x reference)
#include <cuda_runtime.h>
#include <cstdint>

#define N_LEVELS 12
#define LOG2_T 19
#define TBL_SIZE (1u << LOG2_T)      // 524288 entries per level
#define TMASK (TBL_SIZE - 1u)
#define N_FEATURES 2
#define N_PTS 1048576

#define P1 2654435761u
#define P2 805459861u

// floor(16 * 1.38^l) for l in [0,12)
__device__ __constant__ int kRes[N_LEVELS] = {16, 22, 30, 42, 58, 80, 110, 152, 210, 290, 400, 553};

__device__ __forceinline__ uint32_t hash3(uint32_t cx, uint32_t cy, uint32_t cz) {
    return (cx ^ (cy * P1) ^ (cz * P2)) & TMASK;
}

__global__ void __launch_bounds__(256) hashgrid_kernel(
    const float* __restrict__ x,
    const float* __restrict__ tables,
    float* __restrict__ out)
{
    const int i = blockIdx.x * blockDim.x + threadIdx.x;
    if (i >= N_PTS) return;

    const float px = x[3 * i + 0];
    const float py = x[3 * i + 1];
    const float pz = x[3 * i + 2];

    float result[N_LEVELS * N_FEATURES];

    const int res_host[N_LEVELS] = {16, 22, 30, 42, 58, 80, 110, 152, 210, 290, 400, 553};

    #pragma unroll
    for (int l = 0; l < N_LEVELS; l++) {
        const float res = (float)res_host[l];

        const float sx = px * res;
        const float sy = py * res;
        const float sz = pz * res;
        const float fx = floorf(sx);
        const float fy = floorf(sy);
        const float fz = floorf(sz);
        const float wx = sx - fx;
        const float wy = sy - fy;
        const float wz = sz - fz;

        const uint32_t xi = (uint32_t)fx;
        const uint32_t yi = (uint32_t)fy;
        const uint32_t zi = (uint32_t)fz;

        const uint32_t hy0 = yi * P1;
        const uint32_t hy1 = (yi + 1u) * P1;
        const uint32_t hz0 = zi * P2;
        const uint32_t hz1 = (zi + 1u) * P2;
        const uint32_t x0 = xi;
        const uint32_t x1 = xi + 1u;

        const float2* __restrict__ tab =
            (const float2*)(tables + (size_t)l * TBL_SIZE * N_FEATURES);

        // Corner order matches _OFFSETS: (dx,dy,dz) =
        // 000, 100, 010, 110, 001, 101, 011, 111
        const uint32_t i000 = (x0 ^ hy0 ^ hz0) & TMASK;
        const uint32_t i100 = (x1 ^ hy0 ^ hz0) & TMASK;
        const uint32_t i010 = (x0 ^ hy1 ^ hz0) & TMASK;
        const uint32_t i110 = (x1 ^ hy1 ^ hz0) & TMASK;
        const uint32_t i001 = (x0 ^ hy0 ^ hz1) & TMASK;
        const uint32_t i101 = (x1 ^ hy0 ^ hz1) & TMASK;
        const uint32_t i011 = (x0 ^ hy1 ^ hz1) & TMASK;
        const uint32_t i111 = (x1 ^ hy1 ^ hz1) & TMASK;

        // Issue all 8 gathers before consuming (MLP)
        const float2 f000 = __ldg(tab + i000);
        const float2 f100 = __ldg(tab + i100);
        const float2 f010 = __ldg(tab + i010);
        const float2 f110 = __ldg(tab + i110);
        const float2 f001 = __ldg(tab + i001);
        const float2 f101 = __ldg(tab + i101);
        const float2 f011 = __ldg(tab + i011);
        const float2 f111 = __ldg(tab + i111);

        const float ux = 1.0f - wx;
        const float uy = 1.0f - wy;
        const float uz = 1.0f - wz;

        const float w000 = ux * uy * uz;
        const float w100 = wx * uy * uz;
        const float w010 = ux * wy * uz;
        const float w110 = wx * wy * uz;
        const float w001 = ux * uy * wz;
        const float w101 = wx * uy * wz;
        const float w011 = ux * wy * wz;
        const float w111 = wx * wy * wz;

        float acc0 = w000 * f000.x;
        float acc1 = w000 * f000.y;
        acc0 += w100 * f100.x;  acc1 += w100 * f100.y;
        acc0 += w010 * f010.x;  acc1 += w010 * f010.y;
        acc0 += w110 * f110.x;  acc1 += w110 * f110.y;
        acc0 += w001 * f001.x;  acc1 += w001 * f001.y;
        acc0 += w101 * f101.x;  acc1 += w101 * f101.y;
        acc0 += w011 * f011.x;  acc1 += w011 * f011.y;
        acc0 += w111 * f111.x;  acc1 += w111 * f111.y;

        result[2 * l + 0] = acc0;
        result[2 * l + 1] = acc1;
    }

    // 24 floats = 96 bytes per point, 16B-aligned -> 6 x float4 stores
    float4* __restrict__ o = (float4*)(out + (size_t)i * (N_LEVELS * N_FEATURES));
    #pragma unroll
    for (int k = 0; k < 6; k++) {
        float4 v;
        v.x = result[4 * k + 0];
        v.y = result[4 * k + 1];
        v.z = result[4 * k + 2];
        v.w = result[4 * k + 3];
        o[k] = v;
    }
}

extern "C" void kernel_launch(void* const* d_in, const int* in_sizes, int n_in,
                              void* d_out, int out_size) {
    const float* x      = (const float*)d_in[0];
    const float* tables = (const float*)d_in[1];
    float* out          = (float*)d_out;

    const int threads = 256;
    const int blocks = (N_PTS + threads - 1) / threads;
    hashgrid_kernel<<<blocks, threads>>>(x, tables, out);
}

// round 2
// speedup vs baseline: 1.2828x; 1.2828x over previous
#include <cuda_runtime.h>
#include <cstdint>

#define N_LEVELS 12
#define LOG2_T 19
#define TBL_SIZE (1u << LOG2_T)      // 524288 entries per level
#define TMASK (TBL_SIZE - 1u)
#define N_FEATURES 2
#define N_PTS 1048576

#define P1 2654435761u
#define P2 805459861u

#define SORT_RES 32
#define NB (SORT_RES * SORT_RES * SORT_RES)   // 32768 Morton buckets

// Scratch (no cudaMalloc allowed) — static device globals.
__device__ uint32_t g_perm[N_PTS];
__device__ uint32_t g_hist[NB];
__device__ uint32_t g_off[NB];

__device__ __forceinline__ uint32_t part1by2(uint32_t v) {
    v &= 0x3FFu;
    v = (v | (v << 16)) & 0x030000FFu;
    v = (v | (v << 8))  & 0x0300F00Fu;
    v = (v | (v << 4))  & 0x030C30C3u;
    v = (v | (v << 2))  & 0x09249249u;
    return v;
}

__device__ __forceinline__ uint32_t bucket_key(float px, float py, float pz) {
    uint32_t cx = min((uint32_t)(px * (float)SORT_RES), (uint32_t)(SORT_RES - 1));
    uint32_t cy = min((uint32_t)(py * (float)SORT_RES), (uint32_t)(SORT_RES - 1));
    uint32_t cz = min((uint32_t)(pz * (float)SORT_RES), (uint32_t)(SORT_RES - 1));
    return part1by2(cx) | (part1by2(cy) << 1) | (part1by2(cz) << 2);
}

__global__ void zero_hist_kernel() {
    int i = blockIdx.x * blockDim.x + threadIdx.x;
    if (i < NB) g_hist[i] = 0u;
}

__global__ void hist_kernel(const float* __restrict__ x) {
    int i = blockIdx.x * blockDim.x + threadIdx.x;
    if (i >= N_PTS) return;
    uint32_t key = bucket_key(x[3 * i], x[3 * i + 1], x[3 * i + 2]);
    atomicAdd(&g_hist[key], 1u);
}

// Exclusive scan of 32768 bins: one block, 1024 threads x 32 bins each.
__global__ void __launch_bounds__(1024) scan_kernel() {
    __shared__ uint32_t s[1024];
    const int t = threadIdx.x;
    const int base = t * 32;

    uint32_t vals[32];
    uint32_t tot = 0;
    #pragma unroll
    for (int k = 0; k < 32; k++) {
        vals[k] = g_hist[base + k];
        tot += vals[k];
    }
    s[t] = tot;
    __syncthreads();

    // inclusive Hillis-Steele scan over thread totals
    for (int off = 1; off < 1024; off <<= 1) {
        uint32_t v = (t >= off) ? s[t - off] : 0u;
        __syncthreads();
        s[t] += v;
        __syncthreads();
    }

    uint32_t run = s[t] - tot;   // exclusive prefix for this thread's chunk
    #pragma unroll
    for (int k = 0; k < 32; k++) {
        g_off[base + k] = run;
        run += vals[k];
    }
}

// Scatter point indices into sorted order. Atomic order within a bucket is
// nondeterministic, but every point is computed independently and written to
// its own original output slot, so d_out bits are order-invariant.
__global__ void scatter_kernel(const float* __restrict__ x) {
    int i = blockIdx.x * blockDim.x + threadIdx.x;
    if (i >= N_PTS) return;
    uint32_t key = bucket_key(x[3 * i], x[3 * i + 1], x[3 * i + 2]);
    uint32_t pos = atomicAdd(&g_off[key], 1u);
    g_perm[pos] = (uint32_t)i;
}

__global__ void __launch_bounds__(256) hashgrid_kernel(
    const float* __restrict__ x,
    const float* __restrict__ tables,
    float* __restrict__ out)
{
    const int i = blockIdx.x * blockDim.x + threadIdx.x;
    if (i >= N_PTS) return;

    const uint32_t j = g_perm[i];   // spatially clustered point index

    const float px = x[3 * j + 0];
    const float py = x[3 * j + 1];
    const float pz = x[3 * j + 2];

    float result[N_LEVELS * N_FEATURES];

    const int res_host[N_LEVELS] = {16, 22, 30, 42, 58, 80, 110, 152, 210, 290, 400, 553};

    #pragma unroll
    for (int l = 0; l < N_LEVELS; l++) {
        const float res = (float)res_host[l];

        const float sx = px * res;
        const float sy = py * res;
        const float sz = pz * res;
        const float fx = floorf(sx);
        const float fy = floorf(sy);
        const float fz = floorf(sz);
        const float wx = sx - fx;
        const float wy = sy - fy;
        const float wz = sz - fz;

        const uint32_t xi = (uint32_t)fx;
        const uint32_t yi = (uint32_t)fy;
        const uint32_t zi = (uint32_t)fz;

        const uint32_t hy0 = yi * P1;
        const uint32_t hy1 = (yi + 1u) * P1;
        const uint32_t hz0 = zi * P2;
        const uint32_t hz1 = (zi + 1u) * P2;
        const uint32_t x0 = xi;
        const uint32_t x1 = xi + 1u;

        const float2* __restrict__ tab =
            (const float2*)(tables + (size_t)l * TBL_SIZE * N_FEATURES);

        const uint32_t i000 = (x0 ^ hy0 ^ hz0) & TMASK;
        const uint32_t i100 = (x1 ^ hy0 ^ hz0) & TMASK;
        const uint32_t i010 = (x0 ^ hy1 ^ hz0) & TMASK;
        const uint32_t i110 = (x1 ^ hy1 ^ hz0) & TMASK;
        const uint32_t i001 = (x0 ^ hy0 ^ hz1) & TMASK;
        const uint32_t i101 = (x1 ^ hy0 ^ hz1) & TMASK;
        const uint32_t i011 = (x0 ^ hy1 ^ hz1) & TMASK;
        const uint32_t i111 = (x1 ^ hy1 ^ hz1) & TMASK;

        const float2 f000 = __ldg(tab + i000);
        const float2 f100 = __ldg(tab + i100);
        const float2 f010 = __ldg(tab + i010);
        const float2 f110 = __ldg(tab + i110);
        const float2 f001 = __ldg(tab + i001);
        const float2 f101 = __ldg(tab + i101);
        const float2 f011 = __ldg(tab + i011);
        const float2 f111 = __ldg(tab + i111);

        const float ux = 1.0f - wx;
        const float uy = 1.0f - wy;
        const float uz = 1.0f - wz;

        const float w000 = ux * uy * uz;
        const float w100 = wx * uy * uz;
        const float w010 = ux * wy * uz;
        const float w110 = wx * wy * uz;
        const float w001 = ux * uy * wz;
        const float w101 = wx * uy * wz;
        const float w011 = ux * wy * wz;
        const float w111 = wx * wy * wz;

        float acc0 = w000 * f000.x;
        float acc1 = w000 * f000.y;
        acc0 += w100 * f100.x;  acc1 += w100 * f100.y;
        acc0 += w010 * f010.x;  acc1 += w010 * f010.y;
        acc0 += w110 * f110.x;  acc1 += w110 * f110.y;
        acc0 += w001 * f001.x;  acc1 += w001 * f001.y;
        acc0 += w101 * f101.x;  acc1 += w101 * f101.y;
        acc0 += w011 * f011.x;  acc1 += w011 * f011.y;
        acc0 += w111 * f111.x;  acc1 += w111 * f111.y;

        result[2 * l + 0] = acc0;
        result[2 * l + 1] = acc1;
    }

    // Scattered 96B store to the point's original slot (6 x float4).
    float4* __restrict__ o = (float4*)(out + (size_t)j * (N_LEVELS * N_FEATURES));
    #pragma unroll
    for (int k = 0; k < 6; k++) {
        float4 v;
        v.x = result[4 * k + 0];
        v.y = result[4 * k + 1];
        v.z = result[4 * k + 2];
        v.w = result[4 * k + 3];
        o[k] = v;
    }
}

extern "C" void kernel_launch(void* const* d_in, const int* in_sizes, int n_in,
                              void* d_out, int out_size) {
    const float* x      = (const float*)d_in[0];
    const float* tables = (const float*)d_in[1];
    float* out          = (float*)d_out;

    const int threads = 256;
    const int blocks = (N_PTS + threads - 1) / threads;

    zero_hist_kernel<<<(NB + 255) / 256, 256>>>();
    hist_kernel<<<blocks, threads>>>(x);
    scan_kernel<<<1, 1024>>>();
    scatter_kernel<<<blocks, threads>>>(x);
    hashgrid_kernel<<<blocks, threads>>>(x, tables, out);
}

// round 3
// speedup vs baseline: 1.3170x; 1.0266x over previous
#include <cuda_runtime.h>
#include <cstdint>

#define N_LEVELS 12
#define LOG2_T 19
#define TBL_SIZE (1u << LOG2_T)
#define TMASK (TBL_SIZE - 1u)
#define N_FEATURES 2
#define N_PTS 1048576

#define P1 2654435761u
#define P2 805459861u

#define SORT_RES 32
#define NB (SORT_RES * SORT_RES * SORT_RES)

__device__ uint32_t g_perm[N_PTS];
__device__ uint32_t g_key[N_PTS];
__device__ uint32_t g_hist[NB];
__device__ uint32_t g_off[NB];

__device__ __forceinline__ uint32_t part1by2(uint32_t v) {
    v &= 0x3FFu;
    v = (v | (v << 16)) & 0x030000FFu;
    v = (v | (v << 8))  & 0x0300F00Fu;
    v = (v | (v << 4))  & 0x030C30C3u;
    v = (v | (v << 2))  & 0x09249249u;
    return v;
}

__device__ __forceinline__ uint32_t bucket_key(float px, float py, float pz) {
    uint32_t cx = min((uint32_t)(px * (float)SORT_RES), (uint32_t)(SORT_RES - 1));
    uint32_t cy = min((uint32_t)(py * (float)SORT_RES), (uint32_t)(SORT_RES - 1));
    uint32_t cz = min((uint32_t)(pz * (float)SORT_RES), (uint32_t)(SORT_RES - 1));
    return part1by2(cx) | (part1by2(cy) << 1) | (part1by2(cz) << 2);
}

__global__ void zero_hist_kernel() {
    int i = blockIdx.x * blockDim.x + threadIdx.x;
    if (i < NB) g_hist[i] = 0u;
}

// Compute key once, cache it, build histogram.
__global__ void hist_kernel(const float* __restrict__ x) {
    int i = blockIdx.x * blockDim.x + threadIdx.x;
    if (i >= N_PTS) return;
    uint32_t key = bucket_key(x[3 * i], x[3 * i + 1], x[3 * i + 2]);
    g_key[i] = key;
    atomicAdd(&g_hist[key], 1u);
}

// Exclusive scan of 32768 bins: one block, 1024 threads x 32 bins each.
__global__ void __launch_bounds__(1024) scan_kernel() {
    __shared__ uint32_t s[1024];
    const int t = threadIdx.x;
    const int base = t * 32;

    uint32_t vals[32];
    uint32_t tot = 0;
    #pragma unroll
    for (int k = 0; k < 32; k++) {
        vals[k] = g_hist[base + k];
        tot += vals[k];
    }
    s[t] = tot;
    __syncthreads();

    for (int off = 1; off < 1024; off <<= 1) {
        uint32_t v = (t >= off) ? s[t - off] : 0u;
        __syncthreads();
        s[t] += v;
        __syncthreads();
    }

    uint32_t run = s[t] - tot;
    #pragma unroll
    for (int k = 0; k < 32; k++) {
        g_off[base + k] = run;
        run += vals[k];
    }
}

// Scatter using cached keys (4B read/point instead of 12B + key math).
// Atomic order within a bucket is nondeterministic, but every point is
// computed independently and written to its own original output slot,
// so d_out bits are order-invariant.
__global__ void scatter_kernel() {
    int i = blockIdx.x * blockDim.x + threadIdx.x;
    if (i >= N_PTS) return;
    uint32_t pos = atomicAdd(&g_off[g_key[i]], 1u);
    g_perm[pos] = (uint32_t)i;
}

__global__ void __launch_bounds__(256) hashgrid_kernel(
    const float* __restrict__ x,
    const float* __restrict__ tables,
    float* __restrict__ out)
{
    const int i = blockIdx.x * blockDim.x + threadIdx.x;
    if (i >= N_PTS) return;

    const uint32_t j = g_perm[i];   // spatially clustered point index

    const float px = x[3 * j + 0];
    const float py = x[3 * j + 1];
    const float pz = x[3 * j + 2];

    float result[N_LEVELS * N_FEATURES];

    const int res_host[N_LEVELS] = {16, 22, 30, 42, 58, 80, 110, 152, 210, 290, 400, 553};

    #pragma unroll
    for (int l = 0; l < N_LEVELS; l++) {
        const float res = (float)res_host[l];

        const float sx = px * res;
        const float sy = py * res;
        const float sz = pz * res;
        const float fx = floorf(sx);
        const float fy = floorf(sy);
        const float fz = floorf(sz);
        const float wx = sx - fx;
        const float wy = sy - fy;
        const float wz = sz - fz;

        const uint32_t xi = (uint32_t)fx;
        const uint32_t yi = (uint32_t)fy;
        const uint32_t zi = (uint32_t)fz;

        const uint32_t hy0 = yi * P1;
        const uint32_t hy1 = (yi + 1u) * P1;
        const uint32_t hz0 = zi * P2;
        const uint32_t hz1 = (zi + 1u) * P2;
        const uint32_t x0 = xi;
        const uint32_t x1 = xi + 1u;

        const uint32_t m00 = hy0 ^ hz0;
        const uint32_t m10 = hy1 ^ hz0;
        const uint32_t m01 = hy0 ^ hz1;
        const uint32_t m11 = hy1 ^ hz1;

        const uint32_t i000 = (x0 ^ m00) & TMASK;
        const uint32_t i010 = (x0 ^ m10) & TMASK;
        const uint32_t i001 = (x0 ^ m01) & TMASK;
        const uint32_t i011 = (x0 ^ m11) & TMASK;

        const float2* __restrict__ tab =
            (const float2*)(tables + (size_t)l * TBL_SIZE * N_FEATURES);

        float2 f000, f100, f010, f110, f001, f101, f011, f111;

        if ((xi & 1u) == 0u) {
            // x1 = x0 | 1: each dx-pair is consecutive table entries {2k,2k+1}
            // -> one aligned float4 (single sector) per pair.
            const float4* __restrict__ t4 = (const float4*)tab;
            const float4 v00 = __ldg(t4 + (i000 >> 1));
            const float4 v10 = __ldg(t4 + (i010 >> 1));
            const float4 v01 = __ldg(t4 + (i001 >> 1));
            const float4 v11 = __ldg(t4 + (i011 >> 1));

            const bool s00 = (i000 & 1u) != 0u;
            const bool s10 = (i010 & 1u) != 0u;
            const bool s01 = (i001 & 1u) != 0u;
            const bool s11 = (i011 & 1u) != 0u;

            f000 = s00 ? make_float2(v00.z, v00.w) : make_float2(v00.x, v00.y);
            f100 = s00 ? make_float2(v00.x, v00.y) : make_float2(v00.z, v00.w);
            f010 = s10 ? make_float2(v10.z, v10.w) : make_float2(v10.x, v10.y);
            f110 = s10 ? make_float2(v10.x, v10.y) : make_float2(v10.z, v10.w);
            f001 = s01 ? make_float2(v01.z, v01.w) : make_float2(v01.x, v01.y);
            f101 = s01 ? make_float2(v01.x, v01.y) : make_float2(v01.z, v01.w);
            f011 = s11 ? make_float2(v11.z, v11.w) : make_float2(v11.x, v11.y);
            f111 = s11 ? make_float2(v11.x, v11.y) : make_float2(v11.z, v11.w);
        } else {
            const uint32_t i100 = (x1 ^ m00) & TMASK;
            const uint32_t i110 = (x1 ^ m10) & TMASK;
            const uint32_t i101 = (x1 ^ m01) & TMASK;
            const uint32_t i111 = (x1 ^ m11) & TMASK;

            f000 = __ldg(tab + i000);
            f100 = __ldg(tab + i100);
            f010 = __ldg(tab + i010);
            f110 = __ldg(tab + i110);
            f001 = __ldg(tab + i001);
            f101 = __ldg(tab + i101);
            f011 = __ldg(tab + i011);
            f111 = __ldg(tab + i111);
        }

        const float ux = 1.0f - wx;
        const float uy = 1.0f - wy;
        const float uz = 1.0f - wz;

        const float w000 = ux * uy * uz;
        const float w100 = wx * uy * uz;
        const float w010 = ux * wy * uz;
        const float w110 = wx * wy * uz;
        const float w001 = ux * uy * wz;
        const float w101 = wx * uy * wz;
        const float w011 = ux * wy * wz;
        const float w111 = wx * wy * wz;

        float acc0 = w000 * f000.x;
        float acc1 = w000 * f000.y;
        acc0 += w100 * f100.x;  acc1 += w100 * f100.y;
        acc0 += w010 * f010.x;  acc1 += w010 * f010.y;
        acc0 += w110 * f110.x;  acc1 += w110 * f110.y;
        acc0 += w001 * f001.x;  acc1 += w001 * f001.y;
        acc0 += w101 * f101.x;  acc1 += w101 * f101.y;
        acc0 += w011 * f011.x;  acc1 += w011 * f011.y;
        acc0 += w111 * f111.x;  acc1 += w111 * f111.y;

        result[2 * l + 0] = acc0;
        result[2 * l + 1] = acc1;
    }

    float4* __restrict__ o = (float4*)(out + (size_t)j * (N_LEVELS * N_FEATURES));
    #pragma unroll
    for (int k = 0; k < 6; k++) {
        float4 v;
        v.x = result[4 * k + 0];
        v.y = result[4 * k + 1];
        v.z = result[4 * k + 2];
        v.w = result[4 * k + 3];
        o[k] = v;
    }
}

extern "C" void kernel_launch(void* const* d_in, const int* in_sizes, int n_in,
                              void* d_out, int out_size) {
    const float* x      = (const float*)d_in[0];
    const float* tables = (const float*)d_in[1];
    float* out          = (float*)d_out;

    const int threads = 256;
    const int blocks = (N_PTS + threads - 1) / threads;

    zero_hist_kernel<<<(NB + 255) / 256, 256>>>();
    hist_kernel<<<blocks, threads>>>(x);
    scan_kernel<<<1, 1024>>>();
    scatter_kernel<<<blocks, threads>>>();
    hashgrid_kernel<<<blocks, threads>>>(x, tables, out);
}

// round 4
// speedup vs baseline: 1.3213x; 1.0033x over previous
#include <cuda_runtime.h>
#include <cstdint>

#define N_LEVELS 12
#define LOG2_T 19
#define TBL_SIZE (1u << LOG2_T)
#define TMASK (TBL_SIZE - 1u)
#define N_FEATURES 2
#define N_PTS 1048576

#define P1 2654435761u
#define P2 805459861u

#define SORT_RES 32
#define NB (SORT_RES * SORT_RES * SORT_RES)

__device__ uint32_t g_perm[N_PTS];
__device__ uint32_t g_key[N_PTS];
__device__ uint32_t g_rank[N_PTS];
__device__ uint32_t g_hist[NB];
__device__ uint32_t g_off[NB];

__device__ __forceinline__ uint32_t part1by2(uint32_t v) {
    v &= 0x3FFu;
    v = (v | (v << 16)) & 0x030000FFu;
    v = (v | (v << 8))  & 0x0300F00Fu;
    v = (v | (v << 4))  & 0x030C30C3u;
    v = (v | (v << 2))  & 0x09249249u;
    return v;
}

__device__ __forceinline__ uint32_t bucket_key(float px, float py, float pz) {
    uint32_t cx = min((uint32_t)(px * (float)SORT_RES), (uint32_t)(SORT_RES - 1));
    uint32_t cy = min((uint32_t)(py * (float)SORT_RES), (uint32_t)(SORT_RES - 1));
    uint32_t cz = min((uint32_t)(pz * (float)SORT_RES), (uint32_t)(SORT_RES - 1));
    return part1by2(cx) | (part1by2(cy) << 1) | (part1by2(cz) << 2);
}

// Compute key once, cache key AND intra-bucket rank (atomicAdd return value).
__global__ void hist_kernel(const float* __restrict__ x) {
    int i = blockIdx.x * blockDim.x + threadIdx.x;
    if (i >= N_PTS) return;
    uint32_t key = bucket_key(x[3 * i], x[3 * i + 1], x[3 * i + 2]);
    uint32_t rank = atomicAdd(&g_hist[key], 1u);
    g_key[i] = key;
    g_rank[i] = rank;
}

// Exclusive scan of 32768 bins: one block, 1024 threads x 32 bins each.
__global__ void __launch_bounds__(1024) scan_kernel() {
    __shared__ uint32_t s[1024];
    const int t = threadIdx.x;
    const int base = t * 32;

    uint32_t vals[32];
    uint32_t tot = 0;
    #pragma unroll
    for (int k = 0; k < 32; k++) {
        vals[k] = g_hist[base + k];
        tot += vals[k];
    }
    s[t] = tot;
    __syncthreads();

    for (int off = 1; off < 1024; off <<= 1) {
        uint32_t v = (t >= off) ? s[t - off] : 0u;
        __syncthreads();
        s[t] += v;
        __syncthreads();
    }

    uint32_t run = s[t] - tot;
    #pragma unroll
    for (int k = 0; k < 32; k++) {
        g_off[base + k] = run;
        run += vals[k];
    }
}

// Atomic-free scatter: position = bucket base + cached rank.
// Rank assignment order (from hist_kernel's atomics) is nondeterministic, but
// g_perm is always a valid permutation and every point's output is computed
// independently into its own original slot, so d_out bits are order-invariant.
__global__ void scatter_kernel() {
    int i = blockIdx.x * blockDim.x + threadIdx.x;
    if (i >= N_PTS) return;
    uint32_t pos = g_off[g_key[i]] + g_rank[i];
    g_perm[pos] = (uint32_t)i;
}

__global__ void __launch_bounds__(256) hashgrid_kernel(
    const float* __restrict__ x,
    const float* __restrict__ tables,
    float* __restrict__ out)
{
    const int i = blockIdx.x * blockDim.x + threadIdx.x;
    if (i >= N_PTS) return;

    const uint32_t j = g_perm[i];   // spatially clustered point index

    const float px = x[3 * j + 0];
    const float py = x[3 * j + 1];
    const float pz = x[3 * j + 2];

    float result[N_LEVELS * N_FEATURES];

    const int res_host[N_LEVELS] = {16, 22, 30, 42, 58, 80, 110, 152, 210, 290, 400, 553};

    #pragma unroll
    for (int l = 0; l < N_LEVELS; l++) {
        const float res = (float)res_host[l];

        const float sx = px * res;
        const float sy = py * res;
        const float sz = pz * res;
        const float fx = floorf(sx);
        const float fy = floorf(sy);
        const float fz = floorf(sz);
        const float wx = sx - fx;
        const float wy = sy - fy;
        const float wz = sz - fz;

        const uint32_t xi = (uint32_t)fx;
        const uint32_t yi = (uint32_t)fy;
        const uint32_t zi = (uint32_t)fz;

        const uint32_t hy0 = yi * P1;
        const uint32_t hy1 = (yi + 1u) * P1;
        const uint32_t hz0 = zi * P2;
        const uint32_t hz1 = (zi + 1u) * P2;
        const uint32_t x0 = xi;
        const uint32_t x1 = xi + 1u;

        const uint32_t m00 = hy0 ^ hz0;
        const uint32_t m10 = hy1 ^ hz0;
        const uint32_t m01 = hy0 ^ hz1;
        const uint32_t m11 = hy1 ^ hz1;

        const uint32_t i000 = (x0 ^ m00) & TMASK;
        const uint32_t i010 = (x0 ^ m10) & TMASK;
        const uint32_t i001 = (x0 ^ m01) & TMASK;
        const uint32_t i011 = (x0 ^ m11) & TMASK;

        const float2* __restrict__ tab =
            (const float2*)(tables + (size_t)l * TBL_SIZE * N_FEATURES);

        float2 f000, f100, f010, f110, f001, f101, f011, f111;

        if ((xi & 1u) == 0u) {
            // x1 = x0 | 1: each dx-pair is consecutive table entries {2k,2k+1}
            // -> one aligned float4 per pair.
            const float4* __restrict__ t4 = (const float4*)tab;
            const float4 v00 = __ldg(t4 + (i000 >> 1));
            const float4 v10 = __ldg(t4 + (i010 >> 1));
            const float4 v01 = __ldg(t4 + (i001 >> 1));
            const float4 v11 = __ldg(t4 + (i011 >> 1));

            const bool s00 = (i000 & 1u) != 0u;
            const bool s10 = (i010 & 1u) != 0u;
            const bool s01 = (i001 & 1u) != 0u;
            const bool s11 = (i011 & 1u) != 0u;

            f000 = s00 ? make_float2(v00.z, v00.w) : make_float2(v00.x, v00.y);
            f100 = s00 ? make_float2(v00.x, v00.y) : make_float2(v00.z, v00.w);
            f010 = s10 ? make_float2(v10.z, v10.w) : make_float2(v10.x, v10.y);
            f110 = s10 ? make_float2(v10.x, v10.y) : make_float2(v10.z, v10.w);
            f001 = s01 ? make_float2(v01.z, v01.w) : make_float2(v01.x, v01.y);
            f101 = s01 ? make_float2(v01.x, v01.y) : make_float2(v01.z, v01.w);
            f011 = s11 ? make_float2(v11.z, v11.w) : make_float2(v11.x, v11.y);
            f111 = s11 ? make_float2(v11.x, v11.y) : make_float2(v11.z, v11.w);
        } else {
            const uint32_t i100 = (x1 ^ m00) & TMASK;
            const uint32_t i110 = (x1 ^ m10) & TMASK;
            const uint32_t i101 = (x1 ^ m01) & TMASK;
            const uint32_t i111 = (x1 ^ m11) & TMASK;

            f000 = __ldg(tab + i000);
            f100 = __ldg(tab + i100);
            f010 = __ldg(tab + i010);
            f110 = __ldg(tab + i110);
            f001 = __ldg(tab + i001);
            f101 = __ldg(tab + i101);
            f011 = __ldg(tab + i011);
            f111 = __ldg(tab + i111);
        }

        const float ux = 1.0f - wx;
        const float uy = 1.0f - wy;
        const float uz = 1.0f - wz;

        const float w000 = ux * uy * uz;
        const float w100 = wx * uy * uz;
        const float w010 = ux * wy * uz;
        const float w110 = wx * wy * uz;
        const float w001 = ux * uy * wz;
        const float w101 = wx * uy * wz;
        const float w011 = ux * wy * wz;
        const float w111 = wx * wy * wz;

        float acc0 = w000 * f000.x;
        float acc1 = w000 * f000.y;
        acc0 += w100 * f100.x;  acc1 += w100 * f100.y;
        acc0 += w010 * f010.x;  acc1 += w010 * f010.y;
        acc0 += w110 * f110.x;  acc1 += w110 * f110.y;
        acc0 += w001 * f001.x;  acc1 += w001 * f001.y;
        acc0 += w101 * f101.x;  acc1 += w101 * f101.y;
        acc0 += w011 * f011.x;  acc1 += w011 * f011.y;
        acc0 += w111 * f111.x;  acc1 += w111 * f111.y;

        result[2 * l + 0] = acc0;
        result[2 * l + 1] = acc1;
    }

    float4* __restrict__ o = (float4*)(out + (size_t)j * (N_LEVELS * N_FEATURES));
    #pragma unroll
    for (int k = 0; k < 6; k++) {
        float4 v;
        v.x = result[4 * k + 0];
        v.y = result[4 * k + 1];
        v.z = result[4 * k + 2];
        v.w = result[4 * k + 3];
        o[k] = v;
    }
}

extern "C" void kernel_launch(void* const* d_in, const int* in_sizes, int n_in,
                              void* d_out, int out_size) {
    const float* x      = (const float*)d_in[0];
    const float* tables = (const float*)d_in[1];
    float* out          = (float*)d_out;

    const int threads = 256;
    const int blocks = (N_PTS + threads - 1) / threads;

    // Zero the histogram with a memset node (graph-capturable, no alloc).
    void* hist_ptr = nullptr;
    cudaGetSymbolAddress(&hist_ptr, g_hist);
    cudaMemsetAsync(hist_ptr, 0, NB * sizeof(uint32_t));

    hist_kernel<<<blocks, threads>>>(x);
    scan_kernel<<<1, 1024>>>();
    scatter_kernel<<<blocks, threads>>>();
    hashgrid_kernel<<<blocks, threads>>>(x, tables, out);
}

// round 5
// speedup vs baseline: 1.5360x; 1.1625x over previous
#include <cuda_runtime.h>
#include <cstdint>

#define N_LEVELS 12
#define LOG2_T 19
#define TBL_SIZE (1u << LOG2_T)
#define TMASK (TBL_SIZE - 1u)
#define N_FEATURES 2
#define N_PTS 1048576

#define P1 2654435761u
#define P2 805459861u

#define SORT_RES 32
#define NB (SORT_RES * SORT_RES * SORT_RES)   // 32768 buckets, key = 15 bits

__device__ uint32_t g_perm[N_PTS];
__device__ uint32_t g_kr[N_PTS];      // packed: key | (rank << 15)
__device__ uint32_t g_hist[NB];
__device__ uint32_t g_off[NB];

__device__ __forceinline__ uint32_t part1by2(uint32_t v) {
    v &= 0x3FFu;
    v = (v | (v << 16)) & 0x030000FFu;
    v = (v | (v << 8))  & 0x0300F00Fu;
    v = (v | (v << 4))  & 0x030C30C3u;
    v = (v | (v << 2))  & 0x09249249u;
    return v;
}

__device__ __forceinline__ uint32_t bucket_key(float px, float py, float pz) {
    uint32_t cx = min((uint32_t)(px * (float)SORT_RES), (uint32_t)(SORT_RES - 1));
    uint32_t cy = min((uint32_t)(py * (float)SORT_RES), (uint32_t)(SORT_RES - 1));
    uint32_t cz = min((uint32_t)(pz * (float)SORT_RES), (uint32_t)(SORT_RES - 1));
    return part1by2(cx) | (part1by2(cy) << 1) | (part1by2(cz) << 2);
}

// Key + intra-bucket rank (atomicAdd return), packed into one word.
__global__ void hist_kernel(const float* __restrict__ x) {
    int i = blockIdx.x * blockDim.x + threadIdx.x;
    if (i >= N_PTS) return;
    uint32_t key = bucket_key(x[3 * i], x[3 * i + 1], x[3 * i + 2]);
    uint32_t rank = atomicAdd(&g_hist[key], 1u);
    g_kr[i] = key | (rank << 15);
}

// Bank-swizzled smem index: permutes within each aligned 32-word group so that
// (a) coalesced global loops write/read conflict-free, and
// (b) thread t's sequential walk over bins [t*32, t*32+32) is conflict-free.
__device__ __forceinline__ uint32_t swz(uint32_t i) {
    return (i & ~31u) | ((i + (i >> 5)) & 31u);
}

// Exclusive scan of 32768 bins. Single block; all global traffic coalesced via
// a 128KB smem staging buffer.
__global__ void __launch_bounds__(1024) scan_kernel() {
    extern __shared__ uint32_t sh[];      // NB words (128 KB)
    __shared__ uint32_t s[1024];
    const int t = threadIdx.x;

    // Coalesced load of all bins into swizzled smem.
    #pragma unroll
    for (int k = 0; k < 32; k++) {
        uint32_t i = (uint32_t)(k * 1024 + t);
        sh[swz(i)] = g_hist[i];
    }
    __syncthreads();

    // Thread t: sequential read of its 32 consecutive bins (conflict-free).
    uint32_t vals[32];
    uint32_t tot = 0;
    #pragma unroll
    for (int k = 0; k < 32; k++) {
        vals[k] = sh[t * 32 + ((k + t) & 31)];
        tot += vals[k];
    }
    s[t] = tot;
    __syncthreads();

    // Inclusive Hillis-Steele over the 1024 thread totals.
    for (int off = 1; off < 1024; off <<= 1) {
        uint32_t v = (t >= off) ? s[t - off] : 0u;
        __syncthreads();
        s[t] += v;
        __syncthreads();
    }

    // Exclusive offsets written back through the same swizzled layout.
    uint32_t run = s[t] - tot;
    #pragma unroll
    for (int k = 0; k < 32; k++) {
        sh[t * 32 + ((k + t) & 31)] = run;
        run += vals[k];
    }
    __syncthreads();

    #pragma unroll
    for (int k = 0; k < 32; k++) {
        uint32_t i = (uint32_t)(k * 1024 + t);
        g_off[i] = sh[swz(i)];
    }
}

// Atomic-free scatter: position = bucket base + cached rank.
// Rank assignment order (from hist_kernel's atomics) is nondeterministic, but
// g_perm is always a valid permutation and every point's output is computed
// independently into its own original slot, so d_out bits are order-invariant.
__global__ void scatter_kernel() {
    int i = blockIdx.x * blockDim.x + threadIdx.x;
    if (i >= N_PTS) return;
    uint32_t v = g_kr[i];
    uint32_t pos = g_off[v & (NB - 1u)] + (v >> 15);
    g_perm[pos] = (uint32_t)i;
}

__global__ void __launch_bounds__(256) hashgrid_kernel(
    const float* __restrict__ x,
    const float* __restrict__ tables,
    float* __restrict__ out)
{
    const int i = blockIdx.x * blockDim.x + threadIdx.x;
    if (i >= N_PTS) return;

    const uint32_t j = g_perm[i];   // spatially clustered point index

    const float px = x[3 * j + 0];
    const float py = x[3 * j + 1];
    const float pz = x[3 * j + 2];

    float result[N_LEVELS * N_FEATURES];

    const int res_host[N_LEVELS] = {16, 22, 30, 42, 58, 80, 110, 152, 210, 290, 400, 553};

    #pragma unroll
    for (int l = 0; l < N_LEVELS; l++) {
        const float res = (float)res_host[l];

        const float sx = px * res;
        const float sy = py * res;
        const float sz = pz * res;
        const float fx = floorf(sx);
        const float fy = floorf(sy);
        const float fz = floorf(sz);
        const float wx = sx - fx;
        const float wy = sy - fy;
        const float wz = sz - fz;

        const uint32_t xi = (uint32_t)fx;
        const uint32_t yi = (uint32_t)fy;
        const uint32_t zi = (uint32_t)fz;

        const uint32_t hy0 = yi * P1;
        const uint32_t hy1 = (yi + 1u) * P1;
        const uint32_t hz0 = zi * P2;
        const uint32_t hz1 = (zi + 1u) * P2;
        const uint32_t x0 = xi;
        const uint32_t x1 = xi + 1u;

        const uint32_t m00 = hy0 ^ hz0;
        const uint32_t m10 = hy1 ^ hz0;
        const uint32_t m01 = hy0 ^ hz1;
        const uint32_t m11 = hy1 ^ hz1;

        const uint32_t i000 = (x0 ^ m00) & TMASK;
        const uint32_t i010 = (x0 ^ m10) & TMASK;
        const uint32_t i001 = (x0 ^ m01) & TMASK;
        const uint32_t i011 = (x0 ^ m11) & TMASK;

        const float2* __restrict__ tab =
            (const float2*)(tables + (size_t)l * TBL_SIZE * N_FEATURES);

        float2 f000, f100, f010, f110, f001, f101, f011, f111;

        if ((xi & 1u) == 0u) {
            // x1 = x0 | 1: each dx-pair is consecutive table entries {2k,2k+1}
            // -> one aligned float4 per pair.
            const float4* __restrict__ t4 = (const float4*)tab;
            const float4 v00 = __ldg(t4 + (i000 >> 1));
            const float4 v10 = __ldg(t4 + (i010 >> 1));
            const float4 v01 = __ldg(t4 + (i001 >> 1));
            const float4 v11 = __ldg(t4 + (i011 >> 1));

            const bool s00 = (i000 & 1u) != 0u;
            const bool s10 = (i010 & 1u) != 0u;
            const bool s01 = (i001 & 1u) != 0u;
            const bool s11 = (i011 & 1u) != 0u;

            f000 = s00 ? make_float2(v00.z, v00.w) : make_float2(v00.x, v00.y);
            f100 = s00 ? make_float2(v00.x, v00.y) : make_float2(v00.z, v00.w);
            f010 = s10 ? make_float2(v10.z, v10.w) : make_float2(v10.x, v10.y);
            f110 = s10 ? make_float2(v10.x, v10.y) : make_float2(v10.z, v10.w);
            f001 = s01 ? make_float2(v01.z, v01.w) : make_float2(v01.x, v01.y);
            f101 = s01 ? make_float2(v01.x, v01.y) : make_float2(v01.z, v01.w);
            f011 = s11 ? make_float2(v11.z, v11.w) : make_float2(v11.x, v11.y);
            f111 = s11 ? make_float2(v11.x, v11.y) : make_float2(v11.z, v11.w);
        } else {
            const uint32_t i100 = (x1 ^ m00) & TMASK;
            const uint32_t i110 = (x1 ^ m10) & TMASK;
            const uint32_t i101 = (x1 ^ m01) & TMASK;
            const uint32_t i111 = (x1 ^ m11) & TMASK;

            f000 = __ldg(tab + i000);
            f100 = __ldg(tab + i100);
            f010 = __ldg(tab + i010);
            f110 = __ldg(tab + i110);
            f001 = __ldg(tab + i001);
            f101 = __ldg(tab + i101);
            f011 = __ldg(tab + i011);
            f111 = __ldg(tab + i111);
        }

        const float ux = 1.0f - wx;
        const float uy = 1.0f - wy;
        const float uz = 1.0f - wz;

        const float w000 = ux * uy * uz;
        const float w100 = wx * uy * uz;
        const float w010 = ux * wy * uz;
        const float w110 = wx * wy * uz;
        const float w001 = ux * uy * wz;
        const float w101 = wx * uy * wz;
        const float w011 = ux * wy * wz;
        const float w111 = wx * wy * wz;

        float acc0 = w000 * f000.x;
        float acc1 = w000 * f000.y;
        acc0 += w100 * f100.x;  acc1 += w100 * f100.y;
        acc0 += w010 * f010.x;  acc1 += w010 * f010.y;
        acc0 += w110 * f110.x;  acc1 += w110 * f110.y;
        acc0 += w001 * f001.x;  acc1 += w001 * f001.y;
        acc0 += w101 * f101.x;  acc1 += w101 * f101.y;
        acc0 += w011 * f011.x;  acc1 += w011 * f011.y;
        acc0 += w111 * f111.x;  acc1 += w111 * f111.y;

        result[2 * l + 0] = acc0;
        result[2 * l + 1] = acc1;
    }

    float4* __restrict__ o = (float4*)(out + (size_t)j * (N_LEVELS * N_FEATURES));
    #pragma unroll
    for (int k = 0; k < 6; k++) {
        float4 v;
        v.x = result[4 * k + 0];
        v.y = result[4 * k + 1];
        v.z = result[4 * k + 2];
        v.w = result[4 * k + 3];
        o[k] = v;
    }
}

extern "C" void kernel_launch(void* const* d_in, const int* in_sizes, int n_in,
                              void* d_out, int out_size) {
    const float* x      = (const float*)d_in[0];
    const float* tables = (const float*)d_in[1];
    float* out          = (float*)d_out;

    const int threads = 256;
    const int blocks = (N_PTS + threads - 1) / threads;

    static bool attr_set = false;
    if (!attr_set) {
        cudaFuncSetAttribute(scan_kernel,
                             cudaFuncAttributeMaxDynamicSharedMemorySize,
                             NB * sizeof(uint32_t));
        attr_set = true;
    }

    // Zero the histogram with a memset node (graph-capturable, no alloc).
    void* hist_ptr = nullptr;
    cudaGetSymbolAddress(&hist_ptr, g_hist);
    cudaMemsetAsync(hist_ptr, 0, NB * sizeof(uint32_t));

    hist_kernel<<<blocks, threads>>>(x);
    scan_kernel<<<1, 1024, NB * sizeof(uint32_t)>>>();
    scatter_kernel<<<blocks, threads>>>();
    hashgrid_kernel<<<blocks, threads>>>(x, tables, out);
}

// round 6
// speedup vs baseline: 1.5518x; 1.0103x over previous
#include <cuda_runtime.h>
#include <cstdint>

#define N_LEVELS 12
#define LOG2_T 19
#define TBL_SIZE (1u << LOG2_T)
#define TMASK (TBL_SIZE - 1u)
#define N_FEATURES 2
#define N_PTS 1048576

#define P1 2654435761u
#define P2 805459861u

#define SORT_RES 32
#define NB (SORT_RES * SORT_RES * SORT_RES)   // 32768 buckets, key = 15 bits

__device__ uint32_t g_perm[N_PTS];
__device__ uint32_t g_kr[N_PTS];      // packed: key | (rank << 15)
__device__ uint32_t g_hist[NB];
__device__ uint32_t g_off[NB];

__device__ __forceinline__ uint32_t part1by2(uint32_t v) {
    v &= 0x3FFu;
    v = (v | (v << 16)) & 0x030000FFu;
    v = (v | (v << 8))  & 0x0300F00Fu;
    v = (v | (v << 4))  & 0x030C30C3u;
    v = (v | (v << 2))  & 0x09249249u;
    return v;
}

__device__ __forceinline__ uint32_t bucket_key(float px, float py, float pz) {
    uint32_t cx = min((uint32_t)(px * (float)SORT_RES), (uint32_t)(SORT_RES - 1));
    uint32_t cy = min((uint32_t)(py * (float)SORT_RES), (uint32_t)(SORT_RES - 1));
    uint32_t cz = min((uint32_t)(pz * (float)SORT_RES), (uint32_t)(SORT_RES - 1));
    return part1by2(cx) | (part1by2(cy) << 1) | (part1by2(cz) << 2);
}

// Key + intra-bucket rank (atomicAdd return), packed into one word.
__global__ void hist_kernel(const float* __restrict__ x) {
    int i = blockIdx.x * blockDim.x + threadIdx.x;
    if (i >= N_PTS) return;
    uint32_t key = bucket_key(x[3 * i], x[3 * i + 1], x[3 * i + 2]);
    uint32_t rank = atomicAdd(&g_hist[key], 1u);
    g_kr[i] = key | (rank << 15);
}

// Bank-swizzled smem index (see round 5 notes).
__device__ __forceinline__ uint32_t swz(uint32_t i) {
    return (i & ~31u) | ((i + (i >> 5)) & 31u);
}

// Exclusive scan of 32768 bins; all global traffic coalesced via 128KB smem.
__global__ void __launch_bounds__(1024) scan_kernel() {
    extern __shared__ uint32_t sh[];
    __shared__ uint32_t s[1024];
    const int t = threadIdx.x;

    #pragma unroll
    for (int k = 0; k < 32; k++) {
        uint32_t i = (uint32_t)(k * 1024 + t);
        sh[swz(i)] = g_hist[i];
    }
    __syncthreads();

    uint32_t vals[32];
    uint32_t tot = 0;
    #pragma unroll
    for (int k = 0; k < 32; k++) {
        vals[k] = sh[t * 32 + ((k + t) & 31)];
        tot += vals[k];
    }
    s[t] = tot;
    __syncthreads();

    for (int off = 1; off < 1024; off <<= 1) {
        uint32_t v = (t >= off) ? s[t - off] : 0u;
        __syncthreads();
        s[t] += v;
        __syncthreads();
    }

    uint32_t run = s[t] - tot;
    #pragma unroll
    for (int k = 0; k < 32; k++) {
        sh[t * 32 + ((k + t) & 31)] = run;
        run += vals[k];
    }
    __syncthreads();

    #pragma unroll
    for (int k = 0; k < 32; k++) {
        uint32_t i = (uint32_t)(k * 1024 + t);
        g_off[i] = sh[swz(i)];
    }
}

// Atomic-free scatter; perm is a valid permutation regardless of the
// nondeterministic rank order, and d_out is order-invariant.
__global__ void scatter_kernel() {
    int i = blockIdx.x * blockDim.x + threadIdx.x;
    if (i >= N_PTS) return;
    uint32_t v = g_kr[i];
    uint32_t pos = g_off[v & (NB - 1u)] + (v >> 15);
    __stcs(&g_perm[pos], (uint32_t)i);
}

__global__ void __launch_bounds__(256, 5) hashgrid_kernel(
    const float* __restrict__ x,
    const float* __restrict__ tables,
    float* __restrict__ out)
{
    const int i = blockIdx.x * blockDim.x + threadIdx.x;
    if (i >= N_PTS) return;

    const uint32_t j = __ldg(&g_perm[i]);   // spatially clustered point index

    const float px = x[3 * j + 0];
    const float py = x[3 * j + 1];
    const float pz = x[3 * j + 2];

    float4* __restrict__ o = (float4*)(out + (size_t)j * (N_LEVELS * N_FEATURES));

    const int res_host[N_LEVELS] = {16, 22, 30, 42, 58, 80, 110, 152, 210, 290, 400, 553};

    float pend0 = 0.0f, pend1 = 0.0f;   // first half of the current float4

    #pragma unroll
    for (int l = 0; l < N_LEVELS; l++) {
        const float res = (float)res_host[l];

        const float sx = px * res;
        const float sy = py * res;
        const float sz = pz * res;
        const float fx = floorf(sx);
        const float fy = floorf(sy);
        const float fz = floorf(sz);
        const float wx = sx - fx;
        const float wy = sy - fy;
        const float wz = sz - fz;

        const uint32_t xi = (uint32_t)fx;
        const uint32_t yi = (uint32_t)fy;
        const uint32_t zi = (uint32_t)fz;

        const uint32_t hy0 = yi * P1;
        const uint32_t hy1 = (yi + 1u) * P1;
        const uint32_t hz0 = zi * P2;
        const uint32_t hz1 = (zi + 1u) * P2;
        const uint32_t x0 = xi;
        const uint32_t x1 = xi + 1u;

        const uint32_t m00 = hy0 ^ hz0;
        const uint32_t m10 = hy1 ^ hz0;
        const uint32_t m01 = hy0 ^ hz1;
        const uint32_t m11 = hy1 ^ hz1;

        const uint32_t i000 = (x0 ^ m00) & TMASK;
        const uint32_t i010 = (x0 ^ m10) & TMASK;
        const uint32_t i001 = (x0 ^ m01) & TMASK;
        const uint32_t i011 = (x0 ^ m11) & TMASK;

        const float2* __restrict__ tab =
            (const float2*)(tables + (size_t)l * TBL_SIZE * N_FEATURES);

        float2 f000, f100, f010, f110, f001, f101, f011, f111;

        if ((xi & 1u) == 0u) {
            // x1 = x0 | 1: each dx-pair is consecutive entries {2k,2k+1}
            // -> one aligned float4 per pair.
            const float4* __restrict__ t4 = (const float4*)tab;
            const float4 v00 = __ldg(t4 + (i000 >> 1));
            const float4 v10 = __ldg(t4 + (i010 >> 1));
            const float4 v01 = __ldg(t4 + (i001 >> 1));
            const float4 v11 = __ldg(t4 + (i011 >> 1));

            const bool s00 = (i000 & 1u) != 0u;
            const bool s10 = (i010 & 1u) != 0u;
            const bool s01 = (i001 & 1u) != 0u;
            const bool s11 = (i011 & 1u) != 0u;

            f000 = s00 ? make_float2(v00.z, v00.w) : make_float2(v00.x, v00.y);
            f100 = s00 ? make_float2(v00.x, v00.y) : make_float2(v00.z, v00.w);
            f010 = s10 ? make_float2(v10.z, v10.w) : make_float2(v10.x, v10.y);
            f110 = s10 ? make_float2(v10.x, v10.y) : make_float2(v10.z, v10.w);
            f001 = s01 ? make_float2(v01.z, v01.w) : make_float2(v01.x, v01.y);
            f101 = s01 ? make_float2(v01.x, v01.y) : make_float2(v01.z, v01.w);
            f011 = s11 ? make_float2(v11.z, v11.w) : make_float2(v11.x, v11.y);
            f111 = s11 ? make_float2(v11.x, v11.y) : make_float2(v11.z, v11.w);
        } else {
            const uint32_t i100 = (x1 ^ m00) & TMASK;
            const uint32_t i110 = (x1 ^ m10) & TMASK;
            const uint32_t i101 = (x1 ^ m01) & TMASK;
            const uint32_t i111 = (x1 ^ m11) & TMASK;

            f000 = __ldg(tab + i000);
            f100 = __ldg(tab + i100);
            f010 = __ldg(tab + i010);
            f110 = __ldg(tab + i110);
            f001 = __ldg(tab + i001);
            f101 = __ldg(tab + i101);
            f011 = __ldg(tab + i011);
            f111 = __ldg(tab + i111);
        }

        const float ux = 1.0f - wx;
        const float uy = 1.0f - wy;
        const float uz = 1.0f - wz;

        const float w000 = ux * uy * uz;
        const float w100 = wx * uy * uz;
        const float w010 = ux * wy * uz;
        const float w110 = wx * wy * uz;
        const float w001 = ux * uy * wz;
        const float w101 = wx * uy * wz;
        const float w011 = ux * wy * wz;
        const float w111 = wx * wy * wz;

        float acc0 = w000 * f000.x;
        float acc1 = w000 * f000.y;
        acc0 += w100 * f100.x;  acc1 += w100 * f100.y;
        acc0 += w010 * f010.x;  acc1 += w010 * f010.y;
        acc0 += w110 * f110.x;  acc1 += w110 * f110.y;
        acc0 += w001 * f001.x;  acc1 += w001 * f001.y;
        acc0 += w101 * f101.x;  acc1 += w101 * f101.y;
        acc0 += w011 * f011.x;  acc1 += w011 * f011.y;
        acc0 += w111 * f111.x;  acc1 += w111 * f111.y;

        // Flush a float4 every two levels; streaming store (write-once data)
        // so the 100MB output doesn't evict hot table lines from L2.
        if ((l & 1) == 0) {
            pend0 = acc0;
            pend1 = acc1;
        } else {
            __stcs(&o[l >> 1], make_float4(pend0, pend1, acc0, acc1));
        }
    }
}

extern "C" void kernel_launch(void* const* d_in, const int* in_sizes, int n_in,
                              void* d_out, int out_size) {
    const float* x      = (const float*)d_in[0];
    const float* tables = (const float*)d_in[1];
    float* out          = (float*)d_out;

    const int threads = 256;
    const int blocks = (N_PTS + threads - 1) / threads;

    static bool attr_set = false;
    if (!attr_set) {
        cudaFuncSetAttribute(scan_kernel,
                             cudaFuncAttributeMaxDynamicSharedMemorySize,
                             NB * sizeof(uint32_t));
        attr_set = true;
    }

    // Zero the histogram with a memset node (graph-capturable, no alloc).
    void* hist_ptr = nullptr;
    cudaGetSymbolAddress(&hist_ptr, g_hist);
    cudaMemsetAsync(hist_ptr, 0, NB * sizeof(uint32_t));

    hist_kernel<<<blocks, threads>>>(x);
    scan_kernel<<<1, 1024, NB * sizeof(uint32_t)>>>();
    scatter_kernel<<<blocks, threads>>>();
    hashgrid_kernel<<<blocks, threads>>>(x, tables, out);
}

// round 7
// speedup vs baseline: 1.5726x; 1.0134x over previous
#include <cuda_runtime.h>
#include <cstdint>

#define N_LEVELS 12
#define LOG2_T 19
#define TBL_SIZE (1u << LOG2_T)
#define TMASK (TBL_SIZE - 1u)
#define N_FEATURES 2
#define N_PTS 1048576

#define P1 2654435761u
#define P2 805459861u

#define SORT_RES 32
#define NB (SORT_RES * SORT_RES * SORT_RES)   // 32768 buckets, key = 15 bits

__device__ uint32_t g_kr[N_PTS];      // packed: key | (rank << 15)
__device__ uint32_t g_hist[NB];
__device__ uint32_t g_off[NB];
__device__ float4   g_xs[N_PTS];      // sorted points: (x, y, z, bits(orig_idx))

__device__ __forceinline__ uint32_t part1by2(uint32_t v) {
    v &= 0x3FFu;
    v = (v | (v << 16)) & 0x030000FFu;
    v = (v | (v << 8))  & 0x0300F00Fu;
    v = (v | (v << 4))  & 0x030C30C3u;
    v = (v | (v << 2))  & 0x09249249u;
    return v;
}

__device__ __forceinline__ uint32_t bucket_key(float px, float py, float pz) {
    uint32_t cx = min((uint32_t)(px * (float)SORT_RES), (uint32_t)(SORT_RES - 1));
    uint32_t cy = min((uint32_t)(py * (float)SORT_RES), (uint32_t)(SORT_RES - 1));
    uint32_t cz = min((uint32_t)(pz * (float)SORT_RES), (uint32_t)(SORT_RES - 1));
    return part1by2(cx) | (part1by2(cy) << 1) | (part1by2(cz) << 2);
}

// Key + intra-bucket rank (atomicAdd return), packed into one word.
__global__ void hist_kernel(const float* __restrict__ x) {
    int i = blockIdx.x * blockDim.x + threadIdx.x;
    if (i >= N_PTS) return;
    uint32_t key = bucket_key(x[3 * i], x[3 * i + 1], x[3 * i + 2]);
    uint32_t rank = atomicAdd(&g_hist[key], 1u);
    g_kr[i] = key | (rank << 15);
}

// Bank-swizzled smem index (round 5 notes).
__device__ __forceinline__ uint32_t swz(uint32_t i) {
    return (i & ~31u) | ((i + (i >> 5)) & 31u);
}

// Exclusive scan of 32768 bins; all global traffic coalesced via 128KB smem.
__global__ void __launch_bounds__(1024) scan_kernel() {
    extern __shared__ uint32_t sh[];
    __shared__ uint32_t s[1024];
    const int t = threadIdx.x;

    #pragma unroll
    for (int k = 0; k < 32; k++) {
        uint32_t i = (uint32_t)(k * 1024 + t);
        sh[swz(i)] = g_hist[i];
    }
    __syncthreads();

    uint32_t vals[32];
    uint32_t tot = 0;
    #pragma unroll
    for (int k = 0; k < 32; k++) {
        vals[k] = sh[t * 32 + ((k + t) & 31)];
        tot += vals[k];
    }
    s[t] = tot;
    __syncthreads();

    for (int off = 1; off < 1024; off <<= 1) {
        uint32_t v = (t >= off) ? s[t - off] : 0u;
        __syncthreads();
        s[t] += v;
        __syncthreads();
    }

    uint32_t run = s[t] - tot;
    #pragma unroll
    for (int k = 0; k < 32; k++) {
        sh[t * 32 + ((k + t) & 31)] = run;
        run += vals[k];
    }
    __syncthreads();

    #pragma unroll
    for (int k = 0; k < 32; k++) {
        uint32_t i = (uint32_t)(k * 1024 + t);
        g_off[i] = sh[swz(i)];
    }
}

// Atomic-free scatter: write the POINT DATA (plus original index) to its
// sorted slot. Encode then reads points fully coalesced. Rank order from
// hist's atomics is nondeterministic, but g_xs is always the same multiset
// and every point's output goes to its own original slot -> d_out invariant.
__global__ void scatter_kernel(const float* __restrict__ x) {
    int i = blockIdx.x * blockDim.x + threadIdx.x;
    if (i >= N_PTS) return;
    uint32_t v = g_kr[i];
    uint32_t pos = g_off[v & (NB - 1u)] + (v >> 15);
    float4 p;
    p.x = x[3 * i + 0];
    p.y = x[3 * i + 1];
    p.z = x[3 * i + 2];
    p.w = __uint_as_float((uint32_t)i);
    __stcs(&g_xs[pos], p);
}

__global__ void __launch_bounds__(256, 5) hashgrid_kernel(
    const float* __restrict__ tables,
    float* __restrict__ out)
{
    const int i = blockIdx.x * blockDim.x + threadIdx.x;
    if (i >= N_PTS) return;

    // One coalesced 16B load delivers coords + original index.
    const float4 p = __ldg(&g_xs[i]);
    const float px = p.x;
    const float py = p.y;
    const float pz = p.z;
    const uint32_t j = __float_as_uint(p.w);

    float4* __restrict__ o = (float4*)(out + (size_t)j * (N_LEVELS * N_FEATURES));

    const int res_host[N_LEVELS] = {16, 22, 30, 42, 58, 80, 110, 152, 210, 290, 400, 553};

    float pend0 = 0.0f, pend1 = 0.0f;

    #pragma unroll
    for (int l = 0; l < N_LEVELS; l++) {
        const float res = (float)res_host[l];

        const float sx = px * res;
        const float sy = py * res;
        const float sz = pz * res;
        const float fx = floorf(sx);
        const float fy = floorf(sy);
        const float fz = floorf(sz);
        const float wx = sx - fx;
        const float wy = sy - fy;
        const float wz = sz - fz;

        const uint32_t xi = (uint32_t)fx;
        const uint32_t yi = (uint32_t)fy;
        const uint32_t zi = (uint32_t)fz;

        const uint32_t hy0 = yi * P1;
        const uint32_t hy1 = (yi + 1u) * P1;
        const uint32_t hz0 = zi * P2;
        const uint32_t hz1 = (zi + 1u) * P2;
        const uint32_t x0 = xi;
        const uint32_t x1 = xi + 1u;

        const uint32_t m00 = hy0 ^ hz0;
        const uint32_t m10 = hy1 ^ hz0;
        const uint32_t m01 = hy0 ^ hz1;
        const uint32_t m11 = hy1 ^ hz1;

        const uint32_t i000 = (x0 ^ m00) & TMASK;
        const uint32_t i010 = (x0 ^ m10) & TMASK;
        const uint32_t i001 = (x0 ^ m01) & TMASK;
        const uint32_t i011 = (x0 ^ m11) & TMASK;

        const float2* __restrict__ tab =
            (const float2*)(tables + (size_t)l * TBL_SIZE * N_FEATURES);

        float2 f000, f100, f010, f110, f001, f101, f011, f111;

        if ((xi & 1u) == 0u) {
            // x1 = x0 | 1: each dx-pair is consecutive entries {2k,2k+1}
            // -> one aligned float4 per pair.
            const float4* __restrict__ t4 = (const float4*)tab;
            const float4 v00 = __ldg(t4 + (i000 >> 1));
            const float4 v10 = __ldg(t4 + (i010 >> 1));
            const float4 v01 = __ldg(t4 + (i001 >> 1));
            const float4 v11 = __ldg(t4 + (i011 >> 1));

            const bool s00 = (i000 & 1u) != 0u;
            const bool s10 = (i010 & 1u) != 0u;
            const bool s01 = (i001 & 1u) != 0u;
            const bool s11 = (i011 & 1u) != 0u;

            f000 = s00 ? make_float2(v00.z, v00.w) : make_float2(v00.x, v00.y);
            f100 = s00 ? make_float2(v00.x, v00.y) : make_float2(v00.z, v00.w);
            f010 = s10 ? make_float2(v10.z, v10.w) : make_float2(v10.x, v10.y);
            f110 = s10 ? make_float2(v10.x, v10.y) : make_float2(v10.z, v10.w);
            f001 = s01 ? make_float2(v01.z, v01.w) : make_float2(v01.x, v01.y);
            f101 = s01 ? make_float2(v01.x, v01.y) : make_float2(v01.z, v01.w);
            f011 = s11 ? make_float2(v11.z, v11.w) : make_float2(v11.x, v11.y);
            f111 = s11 ? make_float2(v11.x, v11.y) : make_float2(v11.z, v11.w);
        } else {
            const uint32_t i100 = (x1 ^ m00) & TMASK;
            const uint32_t i110 = (x1 ^ m10) & TMASK;
            const uint32_t i101 = (x1 ^ m01) & TMASK;
            const uint32_t i111 = (x1 ^ m11) & TMASK;

            f000 = __ldg(tab + i000);
            f100 = __ldg(tab + i100);
            f010 = __ldg(tab + i010);
            f110 = __ldg(tab + i110);
            f001 = __ldg(tab + i001);
            f101 = __ldg(tab + i101);
            f011 = __ldg(tab + i011);
            f111 = __ldg(tab + i111);
        }

        const float ux = 1.0f - wx;
        const float uy = 1.0f - wy;
        const float uz = 1.0f - wz;

        const float w000 = ux * uy * uz;
        const float w100 = wx * uy * uz;
        const float w010 = ux * wy * uz;
        const float w110 = wx * wy * uz;
        const float w001 = ux * uy * wz;
        const float w101 = wx * uy * wz;
        const float w011 = ux * wy * wz;
        const float w111 = wx * wy * wz;

        float acc0 = w000 * f000.x;
        float acc1 = w000 * f000.y;
        acc0 += w100 * f100.x;  acc1 += w100 * f100.y;
        acc0 += w010 * f010.x;  acc1 += w010 * f010.y;
        acc0 += w110 * f110.x;  acc1 += w110 * f110.y;
        acc0 += w001 * f001.x;  acc1 += w001 * f001.y;
        acc0 += w101 * f101.x;  acc1 += w101 * f101.y;
        acc0 += w011 * f011.x;  acc1 += w011 * f011.y;
        acc0 += w111 * f111.x;  acc1 += w111 * f111.y;

        if ((l & 1) == 0) {
            pend0 = acc0;
            pend1 = acc1;
        } else {
            __stcs(&o[l >> 1], make_float4(pend0, pend1, acc0, acc1));
        }
    }
}

extern "C" void kernel_launch(void* const* d_in, const int* in_sizes, int n_in,
                              void* d_out, int out_size) {
    const float* x      = (const float*)d_in[0];
    const float* tables = (const float*)d_in[1];
    float* out          = (float*)d_out;

    const int threads = 256;
    const int blocks = (N_PTS + threads - 1) / threads;

    static bool attr_set = false;
    if (!attr_set) {
        cudaFuncSetAttribute(scan_kernel,
                             cudaFuncAttributeMaxDynamicSharedMemorySize,
                             NB * sizeof(uint32_t));
        attr_set = true;
    }

    // Zero the histogram with a memset node (graph-capturable, no alloc).
    void* hist_ptr = nullptr;
    cudaGetSymbolAddress(&hist_ptr, g_hist);
    cudaMemsetAsync(hist_ptr, 0, NB * sizeof(uint32_t));

    hist_kernel<<<blocks, threads>>>(x);
    scan_kernel<<<1, 1024, NB * sizeof(uint32_t)>>>();
    scatter_kernel<<<blocks, threads>>>(x);
    hashgrid_kernel<<<blocks, threads>>>(tables, out);
}